// round 14
// baseline (speedup 1.0000x reference)
#include <cuda_runtime.h>
#include <math.h>

#define Bsz 2048
#define Tt  512
#define Vv  64
#define Hh  256
#define HV  320          // H + V
#define BM  16           // batch rows per block (8 per group)
#define BMP 20           // padded row width (floats)
#define NBLK (Bsz / BM)  // 128 blocks
#define NTHR 512         // two independent 256-thread groups
#define NC   (HV / 4)    // 80 k-chunks

// theta packed: g_thetaT4[(k>>2)*(Hh*4) + h*4 + (k&3)]
__device__ __align__(16) float g_thetaT4[HV * Hh];

// ---------- packed f32x2 helpers ----------
__device__ __forceinline__ unsigned long long fma2(unsigned long long a,
                                                   unsigned long long b,
                                                   unsigned long long c) {
    unsigned long long d;
    asm("fma.rn.f32x2 %0, %1, %2, %3;" : "=l"(d) : "l"(a), "l"(b), "l"(c));
    return d;
}
__device__ __forceinline__ unsigned long long pack2(float x) {
    unsigned long long d;
    asm("mov.b64 %0, {%1, %1};" : "=l"(d) : "r"(__float_as_uint(x)));
    return d;
}
__device__ __forceinline__ void unpack2(unsigned long long v, float& lo, float& hi) {
    unsigned int a, b;
    asm("mov.b64 {%0, %1}, %2;" : "=r"(a), "=r"(b) : "l"(v));
    lo = __uint_as_float(a);
    hi = __uint_as_float(b);
}
__device__ __forceinline__ void gbar(int id) {
    asm volatile("bar.sync %0, %1;" :: "r"(id), "r"(256) : "memory");
}

// theta [H, H+V] row-major -> packed chunk layout
__global__ void transpose_kernel(const float* __restrict__ theta) {
    int idx = blockIdx.x * blockDim.x + threadIdx.x;
    if (idx >= HV * Hh) return;
    int k = idx >> 8;
    int h = idx & 255;
    g_thetaT4[(k >> 2) * (Hh * 4) + h * 4 + (k & 3)] = theta[h * HV + k];
}

// Persistent kernel; block = two INDEPENDENT 8-row groups on named barriers.
// Group g (=tid>>8): rows g*8 .. g*8+7.  Within group: hb = gtid&127 -> cols (hb, hb+128);
// r0 = g*8 + (gtid>>7)*4 -> rows r0..r0+3.
__global__ void __launch_bounds__(NTHR, 1) rnn_persistent(
    const float* __restrict__ sf,        // [B, T, V]
    const float* __restrict__ bias_g,    // [1]
    const float* __restrict__ theta_dot, // [1, H]
    float* __restrict__ out)             // [B]
{
    __shared__ __align__(16) float st_p[HV][BMP];   // state+token, k-major: 25.6 KB
    __shared__ __align__(16) float z_s[BM][Hh];     // z scratch: 16 KB
    __shared__ float mean_s[BM];
    __shared__ float rstd_s[BM];

    const int tid  = threadIdx.x;
    const int g    = tid >> 8;           // group 0/1
    const int gtid = tid & 255;
    const int bar  = g + 1;              // named barrier id
    const int hb   = gtid & 127;         // cols (hb, hb+128)
    const int r0   = g * 8 + (gtid >> 7) * 4;   // rows r0..r0+3
    const int wg   = gtid >> 5;          // warp within group (0..7)
    const int lane = gtid & 31;
    const int b0   = blockIdx.x * BM;

    // token mapping (per group): warp wg -> row g*8+wg, lane -> 2 V-values
    const int m_t = g * 8 + wg;
    const int v2  = lane * 2;

    const float bval = bias_g[0];
    const float td0 = theta_dot[hb];
    const float td1 = theta_dot[hb + 128];

    // ---- common prologue (block-wide) ----
    for (int idx = tid; idx < HV * BMP; idx += NTHR)
        (&st_p[0][0])[idx] = 0.0f;
    __syncthreads();
    {
        float2 tk = *reinterpret_cast<const float2*>(
            &sf[((size_t)(b0 + m_t) * Tt + 0) * Vv + v2]);
        st_p[Hh + v2 + 0][m_t] = tk.x;
        st_p[Hh + v2 + 1][m_t] = tk.y;
    }
    __syncthreads();   // after this, groups never sync with each other again

    const float4* th0 = reinterpret_cast<const float4*>(g_thetaT4) + hb;
    const float4* th1 = th0 + 128;

    float zr[8];   // [col(2)][row(4)]

    for (int t = 0; t < Tt; t++) {
        // prefetch next token (overlaps GEMM)
        float2 tok;
        const bool havet = (t + 1 < Tt);
        if (havet) {
            tok = *reinterpret_cast<const float2*>(
                &sf[((size_t)(b0 + m_t) * Tt + (t + 1)) * Vv + v2]);
        }

        // ---------- GEMM: 2 cols x 4 rows per thread ----------
        unsigned long long acc[4];
        acc[0] = acc[1] = acc[2] = acc[3] = pack2(bval);

        // theta software pipeline, depth 2
        float4 a0c = th0[0],  a1c = th1[0];
        float4 a0n = th0[Hh], a1n = th1[Hh];

#pragma unroll 4
        for (int c = 0; c < NC; c++) {
            int cf = (c + 2 < NC) ? c + 2 : c;
            float4 a0f = th0[cf * Hh];
            float4 a1f = th1[cf * Hh];

            // batch st loads: 4 broadcast LDS.128 (rows r0..r0+3 for 4 k's)
            ulonglong2 s[4];
#pragma unroll
            for (int kk = 0; kk < 4; kk++)
                s[kk] = *reinterpret_cast<const ulonglong2*>(&st_p[c * 4 + kk][r0]);

            float t0a[4], t1a[4];
            *reinterpret_cast<float4*>(t0a) = a0c;
            *reinterpret_cast<float4*>(t1a) = a1c;
#pragma unroll
            for (int kk = 0; kk < 4; kk++) {
                unsigned long long p0 = pack2(t0a[kk]);
                unsigned long long p1 = pack2(t1a[kk]);
                acc[0] = fma2(s[kk].x, p0, acc[0]);
                acc[1] = fma2(s[kk].y, p0, acc[1]);
                acc[2] = fma2(s[kk].x, p1, acc[2]);
                acc[3] = fma2(s[kk].y, p1, acc[3]);
            }
            a0c = a0n; a1c = a1n;
            a0n = a0f; a1n = a1f;
        }

        // unpack z, stage into z_s
        unpack2(acc[0], zr[0], zr[1]);
        unpack2(acc[1], zr[2], zr[3]);
        unpack2(acc[2], zr[4], zr[5]);
        unpack2(acc[3], zr[6], zr[7]);
#pragma unroll
        for (int rr = 0; rr < 4; rr++) {
            z_s[r0 + rr][hb]       = zr[rr];
            z_s[r0 + rr][hb + 128] = zr[4 + rr];
        }

        gbar(bar);   // (b) group's z_s ready; group's st_p reads done

        // ---------- per-row mean / Bessel std: warp wg -> row g*8+wg ----------
        {
            const int m = g * 8 + wg;
            float s = 0.0f, ss = 0.0f;
#pragma unroll
            for (int j = 0; j < Hh / 32; j++) {
                float v = z_s[m][j * 32 + lane];
                s += v;
                ss = fmaf(v, v, ss);
            }
#pragma unroll
            for (int off = 16; off; off >>= 1) {
                s  += __shfl_xor_sync(0xffffffffu, s, off);
                ss += __shfl_xor_sync(0xffffffffu, ss, off);
            }
            if (lane == 0) {
                float mean = s * (1.0f / Hh);
                float var  = (ss - (float)Hh * mean * mean) * (1.0f / (Hh - 1));
                var = fmaxf(var, 1e-30f);
                float r = rsqrtf(var);
                r = r * (1.5f - 0.5f * var * r * r);   // Newton refine
                mean_s[m] = mean;
                rstd_s[m] = r;
            }
        }

        // stage next tokens (group's st_p token rows free after bar (b))
        if (havet) {
            st_p[Hh + v2 + 0][m_t] = tok.x;
            st_p[Hh + v2 + 1][m_t] = tok.y;
        }

        gbar(bar);   // (c) group's mean/rstd ready

        // ---------- layernorm apply + relu, write state (STS.128) ----------
        {
            float mn[4], rs[4];
#pragma unroll
            for (int rr = 0; rr < 4; rr++) { mn[rr] = mean_s[r0 + rr]; rs[rr] = rstd_s[r0 + rr]; }
#pragma unroll
            for (int rr = 0; rr < 4; rr++) {
                zr[rr]     = fmaxf((zr[rr]     - mn[rr]) * rs[rr], 0.0f);
                zr[4 + rr] = fmaxf((zr[4 + rr] - mn[rr]) * rs[rr], 0.0f);
            }
            *reinterpret_cast<float4*>(&st_p[hb][r0])       = make_float4(zr[0], zr[1], zr[2], zr[3]);
            *reinterpret_cast<float4*>(&st_p[hb + 128][r0]) = make_float4(zr[4], zr[5], zr[6], zr[7]);
        }

        gbar(bar);   // (d) group's state writes visible before next GEMM
    }

    // ---------- logits ----------
#pragma unroll
    for (int rr = 0; rr < 4; rr++) {
        z_s[r0 + rr][hb]       = zr[rr]     * td0;
        z_s[r0 + rr][hb + 128] = zr[4 + rr] * td1;
    }
    gbar(bar);

    {
        const int m = g * 8 + wg;
        float s = 0.0f;
#pragma unroll
        for (int j = 0; j < Hh / 32; j++) s += z_s[m][j * 32 + lane];
#pragma unroll
        for (int off = 16; off; off >>= 1)
            s += __shfl_xor_sync(0xffffffffu, s, off);
        if (lane == 0) out[b0 + m] = 1.0f / (1.0f + expf(-s));
    }
}

extern "C" void kernel_launch(void* const* d_in, const int* in_sizes, int n_in,
                              void* d_out, int out_size) {
    const float* sf        = (const float*)d_in[0];
    const float* theta     = (const float*)d_in[1];
    const float* bias      = (const float*)d_in[2];
    const float* theta_dot = (const float*)d_in[3];
    float*       out       = (float*)d_out;

    transpose_kernel<<<HV, 256>>>(theta);
    rnn_persistent<<<NBLK, NTHR>>>(sf, bias, theta_dot, out);
}

// round 15
// speedup vs baseline: 1.0002x; 1.0002x over previous
#include <cuda_runtime.h>
#include <math.h>

#define Bsz 2048
#define Tt  512
#define Vv  64
#define Hh  256
#define HV  320          // H + V
#define BM  16           // batch rows per block (8 per group)
#define BMP 20           // padded row width (floats)
#define NBLK (Bsz / BM)  // 128 blocks
#define NTHR 512         // two independent 256-thread groups
#define NC   (HV / 4)    // 80 k-chunks

// theta packed: g_thetaT4[(k>>2)*(Hh*4) + h*4 + (k&3)]
__device__ __align__(16) float g_thetaT4[HV * Hh];

// ---------- packed f32x2 helpers ----------
__device__ __forceinline__ unsigned long long fma2(unsigned long long a,
                                                   unsigned long long b,
                                                   unsigned long long c) {
    unsigned long long d;
    asm("fma.rn.f32x2 %0, %1, %2, %3;" : "=l"(d) : "l"(a), "l"(b), "l"(c));
    return d;
}
__device__ __forceinline__ unsigned long long pack2(float x) {
    unsigned long long d;
    asm("mov.b64 %0, {%1, %1};" : "=l"(d) : "r"(__float_as_uint(x)));
    return d;
}
__device__ __forceinline__ void unpack2(unsigned long long v, float& lo, float& hi) {
    unsigned int a, b;
    asm("mov.b64 {%0, %1}, %2;" : "=r"(a), "=r"(b) : "l"(v));
    lo = __uint_as_float(a);
    hi = __uint_as_float(b);
}
__device__ __forceinline__ void gbar(int id) {
    asm volatile("bar.sync %0, %1;" :: "r"(id), "r"(256) : "memory");
}

// theta [H, H+V] row-major -> packed chunk layout
__global__ void transpose_kernel(const float* __restrict__ theta) {
    int idx = blockIdx.x * blockDim.x + threadIdx.x;
    if (idx >= HV * Hh) return;
    int k = idx >> 8;
    int h = idx & 255;
    g_thetaT4[(k >> 2) * (Hh * 4) + h * 4 + (k & 3)] = theta[h * HV + k];
}

// Persistent kernel; block = two INDEPENDENT 8-row groups on named barriers.
// Group g (=tid>>8): rows g*8 .. g*8+7.  Within group: hb = gtid&127 -> cols (hb, hb+128);
// r0 = g*8 + (gtid>>7)*4 -> rows r0..r0+3.
__global__ void __launch_bounds__(NTHR, 1) rnn_persistent(
    const float* __restrict__ sf,        // [B, T, V]
    const float* __restrict__ bias_g,    // [1]
    const float* __restrict__ theta_dot, // [1, H]
    float* __restrict__ out)             // [B]
{
    __shared__ __align__(16) float st_p[HV][BMP];   // state+token, k-major: 25.6 KB
    __shared__ __align__(16) float z_s[BM][Hh];     // z scratch: 16 KB
    __shared__ float mean_s[BM];
    __shared__ float rstd_s[BM];

    const int tid  = threadIdx.x;
    const int g    = tid >> 8;           // group 0/1
    const int gtid = tid & 255;
    const int bar  = g + 1;              // named barrier id
    const int hb   = gtid & 127;         // cols (hb, hb+128)
    const int r0   = g * 8 + (gtid >> 7) * 4;   // rows r0..r0+3
    const int wg   = gtid >> 5;          // warp within group (0..7)
    const int lane = gtid & 31;
    const int b0   = blockIdx.x * BM;

    // token mapping (per group): warp wg -> row g*8+wg, lane -> 2 V-values
    const int m_t = g * 8 + wg;
    const int v2  = lane * 2;

    const float bval = bias_g[0];
    const float td0 = theta_dot[hb];
    const float td1 = theta_dot[hb + 128];

    // ---- common prologue (block-wide) ----
    for (int idx = tid; idx < HV * BMP; idx += NTHR)
        (&st_p[0][0])[idx] = 0.0f;
    __syncthreads();
    {
        float2 tk = *reinterpret_cast<const float2*>(
            &sf[((size_t)(b0 + m_t) * Tt + 0) * Vv + v2]);
        st_p[Hh + v2 + 0][m_t] = tk.x;
        st_p[Hh + v2 + 1][m_t] = tk.y;
    }
    __syncthreads();   // after this, groups never sync with each other again

    const float4* th0 = reinterpret_cast<const float4*>(g_thetaT4) + hb;
    const float4* th1 = th0 + 128;

    float zr[8];   // [col(2)][row(4)]

    for (int t = 0; t < Tt; t++) {
        // prefetch next token (overlaps GEMM)
        float2 tok;
        const bool havet = (t + 1 < Tt);
        if (havet) {
            tok = *reinterpret_cast<const float2*>(
                &sf[((size_t)(b0 + m_t) * Tt + (t + 1)) * Vv + v2]);
        }

        // ---------- GEMM: 2 cols x 4 rows per thread ----------
        unsigned long long acc[4];
        acc[0] = acc[1] = acc[2] = acc[3] = pack2(bval);

        // theta software pipeline, depth 2
        float4 a0c = th0[0],  a1c = th1[0];
        float4 a0n = th0[Hh], a1n = th1[Hh];

#pragma unroll 4
        for (int c = 0; c < NC; c++) {
            int cf = (c + 2 < NC) ? c + 2 : c;
            float4 a0f = th0[cf * Hh];
            float4 a1f = th1[cf * Hh];

            // batch st loads: 4 broadcast LDS.128 (rows r0..r0+3 for 4 k's)
            ulonglong2 s[4];
#pragma unroll
            for (int kk = 0; kk < 4; kk++)
                s[kk] = *reinterpret_cast<const ulonglong2*>(&st_p[c * 4 + kk][r0]);

            float t0a[4], t1a[4];
            *reinterpret_cast<float4*>(t0a) = a0c;
            *reinterpret_cast<float4*>(t1a) = a1c;
#pragma unroll
            for (int kk = 0; kk < 4; kk++) {
                unsigned long long p0 = pack2(t0a[kk]);
                unsigned long long p1 = pack2(t1a[kk]);
                acc[0] = fma2(s[kk].x, p0, acc[0]);
                acc[1] = fma2(s[kk].y, p0, acc[1]);
                acc[2] = fma2(s[kk].x, p1, acc[2]);
                acc[3] = fma2(s[kk].y, p1, acc[3]);
            }
            a0c = a0n; a1c = a1n;
            a0n = a0f; a1n = a1f;
        }

        // unpack z, stage into z_s
        unpack2(acc[0], zr[0], zr[1]);
        unpack2(acc[1], zr[2], zr[3]);
        unpack2(acc[2], zr[4], zr[5]);
        unpack2(acc[3], zr[6], zr[7]);
#pragma unroll
        for (int rr = 0; rr < 4; rr++) {
            z_s[r0 + rr][hb]       = zr[rr];
            z_s[r0 + rr][hb + 128] = zr[4 + rr];
        }

        gbar(bar);   // (b) group's z_s ready; group's st_p reads done

        // ---------- per-row mean / Bessel std: warp wg -> row g*8+wg ----------
        {
            const int m = g * 8 + wg;
            float s = 0.0f, ss = 0.0f;
#pragma unroll
            for (int j = 0; j < Hh / 32; j++) {
                float v = z_s[m][j * 32 + lane];
                s += v;
                ss = fmaf(v, v, ss);
            }
#pragma unroll
            for (int off = 16; off; off >>= 1) {
                s  += __shfl_xor_sync(0xffffffffu, s, off);
                ss += __shfl_xor_sync(0xffffffffu, ss, off);
            }
            if (lane == 0) {
                float mean = s * (1.0f / Hh);
                float var  = (ss - (float)Hh * mean * mean) * (1.0f / (Hh - 1));
                var = fmaxf(var, 1e-30f);
                float r = rsqrtf(var);
                r = r * (1.5f - 0.5f * var * r * r);   // Newton refine
                mean_s[m] = mean;
                rstd_s[m] = r;
            }
        }

        // stage next tokens (group's st_p token rows free after bar (b))
        if (havet) {
            st_p[Hh + v2 + 0][m_t] = tok.x;
            st_p[Hh + v2 + 1][m_t] = tok.y;
        }

        gbar(bar);   // (c) group's mean/rstd ready

        // ---------- layernorm apply + relu, write state (STS.128) ----------
        {
            float mn[4], rs[4];
#pragma unroll
            for (int rr = 0; rr < 4; rr++) { mn[rr] = mean_s[r0 + rr]; rs[rr] = rstd_s[r0 + rr]; }
#pragma unroll
            for (int rr = 0; rr < 4; rr++) {
                zr[rr]     = fmaxf((zr[rr]     - mn[rr]) * rs[rr], 0.0f);
                zr[4 + rr] = fmaxf((zr[4 + rr] - mn[rr]) * rs[rr], 0.0f);
            }
            *reinterpret_cast<float4*>(&st_p[hb][r0])       = make_float4(zr[0], zr[1], zr[2], zr[3]);
            *reinterpret_cast<float4*>(&st_p[hb + 128][r0]) = make_float4(zr[4], zr[5], zr[6], zr[7]);
        }

        gbar(bar);   // (d) group's state writes visible before next GEMM
    }

    // ---------- logits ----------
#pragma unroll
    for (int rr = 0; rr < 4; rr++) {
        z_s[r0 + rr][hb]       = zr[rr]     * td0;
        z_s[r0 + rr][hb + 128] = zr[4 + rr] * td1;
    }
    gbar(bar);

    {
        const int m = g * 8 + wg;
        float s = 0.0f;
#pragma unroll
        for (int j = 0; j < Hh / 32; j++) s += z_s[m][j * 32 + lane];
#pragma unroll
        for (int off = 16; off; off >>= 1)
            s += __shfl_xor_sync(0xffffffffu, s, off);
        if (lane == 0) out[b0 + m] = 1.0f / (1.0f + expf(-s));
    }
}

extern "C" void kernel_launch(void* const* d_in, const int* in_sizes, int n_in,
                              void* d_out, int out_size) {
    const float* sf        = (const float*)d_in[0];
    const float* theta     = (const float*)d_in[1];
    const float* bias      = (const float*)d_in[2];
    const float* theta_dot = (const float*)d_in[3];
    float*       out       = (float*)d_out;

    transpose_kernel<<<HV, 256>>>(theta);
    rnn_persistent<<<NBLK, NTHR>>>(sf, bias, theta_dot, out);
}

// round 16
// speedup vs baseline: 1.0006x; 1.0004x over previous
#include <cuda_runtime.h>
#include <math.h>

#define Bsz 2048
#define Tt  512
#define Vv  64
#define Hh  256
#define HV  320          // H + V
#define BM  16           // batch rows per block (8 per group)
#define BMP 20           // padded row width (floats)
#define NBLK (Bsz / BM)  // 128 blocks
#define NTHR 512         // two independent 256-thread groups
#define NC   (HV / 4)    // 80 k-chunks

// theta packed: g_thetaT4[(k>>2)*(Hh*4) + h*4 + (k&3)]
__device__ __align__(16) float g_thetaT4[HV * Hh];

// ---------- packed f32x2 helpers ----------
__device__ __forceinline__ unsigned long long fma2(unsigned long long a,
                                                   unsigned long long b,
                                                   unsigned long long c) {
    unsigned long long d;
    asm("fma.rn.f32x2 %0, %1, %2, %3;" : "=l"(d) : "l"(a), "l"(b), "l"(c));
    return d;
}
__device__ __forceinline__ unsigned long long pack2(float x) {
    unsigned long long d;
    asm("mov.b64 %0, {%1, %1};" : "=l"(d) : "r"(__float_as_uint(x)));
    return d;
}
__device__ __forceinline__ void unpack2(unsigned long long v, float& lo, float& hi) {
    unsigned int a, b;
    asm("mov.b64 {%0, %1}, %2;" : "=r"(a), "=r"(b) : "l"(v));
    lo = __uint_as_float(a);
    hi = __uint_as_float(b);
}
__device__ __forceinline__ void gbar(int id) {
    asm volatile("bar.sync %0, %1;" :: "r"(id), "r"(256) : "memory");
}

// theta [H, H+V] row-major -> packed chunk layout
__global__ void transpose_kernel(const float* __restrict__ theta) {
    int idx = blockIdx.x * blockDim.x + threadIdx.x;
    if (idx >= HV * Hh) return;
    int k = idx >> 8;
    int h = idx & 255;
    g_thetaT4[(k >> 2) * (Hh * 4) + h * 4 + (k & 3)] = theta[h * HV + k];
}

// Persistent kernel; block = two INDEPENDENT 8-row groups on named barriers.
// Group g (=tid>>8): rows g*8 .. g*8+7.  Within group: hb = gtid&127 -> cols (hb, hb+128);
// r0 = g*8 + (gtid>>7)*4 -> rows r0..r0+3.
__global__ void __launch_bounds__(NTHR, 1) rnn_persistent(
    const float* __restrict__ sf,        // [B, T, V]
    const float* __restrict__ bias_g,    // [1]
    const float* __restrict__ theta_dot, // [1, H]
    float* __restrict__ out)             // [B]
{
    __shared__ __align__(16) float st_p[HV][BMP];   // state+token, k-major: 25.6 KB
    __shared__ __align__(16) float z_s[BM][Hh];     // z scratch: 16 KB
    __shared__ float mean_s[BM];
    __shared__ float rstd_s[BM];

    const int tid  = threadIdx.x;
    const int g    = tid >> 8;           // group 0/1
    const int gtid = tid & 255;
    const int bar  = g + 1;              // named barrier id
    const int hb   = gtid & 127;         // cols (hb, hb+128)
    const int r0   = g * 8 + (gtid >> 7) * 4;   // rows r0..r0+3
    const int wg   = gtid >> 5;          // warp within group (0..7)
    const int lane = gtid & 31;
    const int b0   = blockIdx.x * BM;

    // token mapping (per group): warp wg -> row g*8+wg, lane -> 2 V-values
    const int m_t = g * 8 + wg;
    const int v2  = lane * 2;

    const float bval = bias_g[0];
    const float td0 = theta_dot[hb];
    const float td1 = theta_dot[hb + 128];

    // ---- common prologue (block-wide) ----
    for (int idx = tid; idx < HV * BMP; idx += NTHR)
        (&st_p[0][0])[idx] = 0.0f;
    __syncthreads();
    {
        float2 tk = *reinterpret_cast<const float2*>(
            &sf[((size_t)(b0 + m_t) * Tt + 0) * Vv + v2]);
        st_p[Hh + v2 + 0][m_t] = tk.x;
        st_p[Hh + v2 + 1][m_t] = tk.y;
    }
    __syncthreads();   // after this, groups never sync with each other again

    const float4* th0 = reinterpret_cast<const float4*>(g_thetaT4) + hb;
    const float4* th1 = th0 + 128;

    float zr[8];   // [col(2)][row(4)]

    for (int t = 0; t < Tt; t++) {
        // prefetch next token (overlaps GEMM)
        float2 tok;
        const bool havet = (t + 1 < Tt);
        if (havet) {
            tok = *reinterpret_cast<const float2*>(
                &sf[((size_t)(b0 + m_t) * Tt + (t + 1)) * Vv + v2]);
        }

        // ---------- GEMM: 2 cols x 4 rows per thread ----------
        unsigned long long acc[4];
        acc[0] = acc[1] = acc[2] = acc[3] = pack2(bval);

        // theta software pipeline, depth 2
        float4 a0c = th0[0],  a1c = th1[0];
        float4 a0n = th0[Hh], a1n = th1[Hh];

#pragma unroll 4
        for (int c = 0; c < NC; c++) {
            int cf = (c + 2 < NC) ? c + 2 : c;
            float4 a0f = th0[cf * Hh];
            float4 a1f = th1[cf * Hh];

            // batch st loads: 4 broadcast LDS.128 (rows r0..r0+3 for 4 k's)
            ulonglong2 s[4];
#pragma unroll
            for (int kk = 0; kk < 4; kk++)
                s[kk] = *reinterpret_cast<const ulonglong2*>(&st_p[c * 4 + kk][r0]);

            float t0a[4], t1a[4];
            *reinterpret_cast<float4*>(t0a) = a0c;
            *reinterpret_cast<float4*>(t1a) = a1c;
#pragma unroll
            for (int kk = 0; kk < 4; kk++) {
                unsigned long long p0 = pack2(t0a[kk]);
                unsigned long long p1 = pack2(t1a[kk]);
                acc[0] = fma2(s[kk].x, p0, acc[0]);
                acc[1] = fma2(s[kk].y, p0, acc[1]);
                acc[2] = fma2(s[kk].x, p1, acc[2]);
                acc[3] = fma2(s[kk].y, p1, acc[3]);
            }
            a0c = a0n; a1c = a1n;
            a0n = a0f; a1n = a1f;
        }

        // unpack z, stage into z_s
        unpack2(acc[0], zr[0], zr[1]);
        unpack2(acc[1], zr[2], zr[3]);
        unpack2(acc[2], zr[4], zr[5]);
        unpack2(acc[3], zr[6], zr[7]);
#pragma unroll
        for (int rr = 0; rr < 4; rr++) {
            z_s[r0 + rr][hb]       = zr[rr];
            z_s[r0 + rr][hb + 128] = zr[4 + rr];
        }

        gbar(bar);   // (b) group's z_s ready; group's st_p reads done

        // ---------- per-row mean / Bessel std: warp wg -> row g*8+wg ----------
        {
            const int m = g * 8 + wg;
            float s = 0.0f, ss = 0.0f;
#pragma unroll
            for (int j = 0; j < Hh / 32; j++) {
                float v = z_s[m][j * 32 + lane];
                s += v;
                ss = fmaf(v, v, ss);
            }
#pragma unroll
            for (int off = 16; off; off >>= 1) {
                s  += __shfl_xor_sync(0xffffffffu, s, off);
                ss += __shfl_xor_sync(0xffffffffu, ss, off);
            }
            if (lane == 0) {
                float mean = s * (1.0f / Hh);
                float var  = (ss - (float)Hh * mean * mean) * (1.0f / (Hh - 1));
                var = fmaxf(var, 1e-30f);
                float r = rsqrtf(var);
                r = r * (1.5f - 0.5f * var * r * r);   // Newton refine
                mean_s[m] = mean;
                rstd_s[m] = r;
            }
        }

        // stage next tokens (group's st_p token rows free after bar (b))
        if (havet) {
            st_p[Hh + v2 + 0][m_t] = tok.x;
            st_p[Hh + v2 + 1][m_t] = tok.y;
        }

        gbar(bar);   // (c) group's mean/rstd ready

        // ---------- layernorm apply + relu, write state (STS.128) ----------
        {
            float mn[4], rs[4];
#pragma unroll
            for (int rr = 0; rr < 4; rr++) { mn[rr] = mean_s[r0 + rr]; rs[rr] = rstd_s[r0 + rr]; }
#pragma unroll
            for (int rr = 0; rr < 4; rr++) {
                zr[rr]     = fmaxf((zr[rr]     - mn[rr]) * rs[rr], 0.0f);
                zr[4 + rr] = fmaxf((zr[4 + rr] - mn[rr]) * rs[rr], 0.0f);
            }
            *reinterpret_cast<float4*>(&st_p[hb][r0])       = make_float4(zr[0], zr[1], zr[2], zr[3]);
            *reinterpret_cast<float4*>(&st_p[hb + 128][r0]) = make_float4(zr[4], zr[5], zr[6], zr[7]);
        }

        gbar(bar);   // (d) group's state writes visible before next GEMM
    }

    // ---------- logits ----------
#pragma unroll
    for (int rr = 0; rr < 4; rr++) {
        z_s[r0 + rr][hb]       = zr[rr]     * td0;
        z_s[r0 + rr][hb + 128] = zr[4 + rr] * td1;
    }
    gbar(bar);

    {
        const int m = g * 8 + wg;
        float s = 0.0f;
#pragma unroll
        for (int j = 0; j < Hh / 32; j++) s += z_s[m][j * 32 + lane];
#pragma unroll
        for (int off = 16; off; off >>= 1)
            s += __shfl_xor_sync(0xffffffffu, s, off);
        if (lane == 0) out[b0 + m] = 1.0f / (1.0f + expf(-s));
    }
}

extern "C" void kernel_launch(void* const* d_in, const int* in_sizes, int n_in,
                              void* d_out, int out_size) {
    const float* sf        = (const float*)d_in[0];
    const float* theta     = (const float*)d_in[1];
    const float* bias      = (const float*)d_in[2];
    const float* theta_dot = (const float*)d_in[3];
    float*       out       = (float*)d_out;

    transpose_kernel<<<HV, 256>>>(theta);
    rnn_persistent<<<NBLK, NTHR>>>(sf, bias, theta_dot, out);
}